// round 6
// baseline (speedup 1.0000x reference)
#include <cuda_runtime.h>
#include <cstdint>

#define BATCH    1024
#define IN_BITS  4096
#define NUM_LUTS 16384
#define KBITS    6
#define NGROUPS  (BATCH / 32)          // 32 groups of 32 batches
#define LTILE    256                   // luts per block
#define NTHR     512                   // 256 LUTs x 2 batch-halves
#define BC       8                     // batch-groups per block

#define PACK_BLOCKS (IN_BITS / 256 * NGROUPS)         // 512
#define SIG_BLOCKS  (NUM_LUTS * 64 / 4 / 256)         // 1024
#define CONN_BLOCKS ((NUM_LUTS * KBITS + 255) / 256)  // 384

__device__ uint32_t g_bits[NGROUPS][IN_BITS];        // 512 KB
__device__ uint16_t g_conn[NUM_LUTS * KBITS];        // 196 KB
__device__ float    g_sig[NUM_LUTS * 64];            // 4 MB

// ---------------------------------------------------------------------------
// Fused prep: [pack | sig | conn] dispatched on blockIdx.x.
// ---------------------------------------------------------------------------
__global__ void __launch_bounds__(256) prep_kernel(const float* __restrict__ x,
                                                   const float* __restrict__ table,
                                                   const int* __restrict__ conn32) {
    const int b = blockIdx.x;
    if (b < PACK_BLOCKS) {
        const int g = b >> 4;
        const int p = (b & 15) * 256 + threadIdx.x;
        const float* xp = x + (size_t)(g * 32) * IN_BITS + p;
        uint32_t a = 0;
#pragma unroll
        for (int j = 0; j < 32; ++j)
            a |= (__ldg(xp + (size_t)j * IN_BITS) > 0.5f ? 1u : 0u) << j;
        g_bits[g][p] = a;
    } else if (b < PACK_BLOCKS + SIG_BLOCKS) {
        const int i = (b - PACK_BLOCKS) * 256 + threadIdx.x;
        float4 v = ((const float4*)table)[i];
        float4 r;
        r.x = __fdividef(1.0f, 1.0f + __expf(-v.x));
        r.y = __fdividef(1.0f, 1.0f + __expf(-v.y));
        r.z = __fdividef(1.0f, 1.0f + __expf(-v.z));
        r.w = __fdividef(1.0f, 1.0f + __expf(-v.w));
        ((float4*)g_sig)[i] = r;
    } else {
        // conn dtype sniff: JAX w/o x64 emits int32 despite int64 annotation;
        // true int64 LE would have all odd words == 0 (values < 4096).
        uint32_t acc = 0;
#pragma unroll
        for (int s = 1; s < 64; s += 2) acc |= (uint32_t)conn32[s];
        const bool is_i64 = (acc == 0u);
        const int i = (b - PACK_BLOCKS - SIG_BLOCKS) * 256 + threadIdx.x;
        if (i < NUM_LUTS * KBITS) {
            int v = is_i64 ? conn32[2 * i] : conn32[i];
            g_conn[i] = (uint16_t)v;
        }
    }
}

// ---------------------------------------------------------------------------
// cp.async helpers
// ---------------------------------------------------------------------------
__device__ __forceinline__ void cp_async16(void* smem_dst, const void* gsrc) {
    uint32_t s = (uint32_t)__cvta_generic_to_shared(smem_dst);
    asm volatile("cp.async.cg.shared.global [%0], [%1], 16;\n" :: "r"(s), "l"(gsrc));
}
__device__ __forceinline__ void cp_async_commit() {
    asm volatile("cp.async.commit_group;\n" ::: "memory");
}
__device__ __forceinline__ void cp_async_wait0() {
    asm volatile("cp.async.wait_group 0;\n" ::: "memory");
}

// ---------------------------------------------------------------------------
// Main LUT kernel. block = 512 = 256 LUTs x 2 batch-halves.
// smem: two 16 KB bit buffers (cp.async double-buffered) + 64 KB table tile
// (256 rows, stride 64 — unpadded; bank = idx%32, same random-conflict stats
// as any pad) = 96 KB -> 2 CTAs/SM (1024 thr, ~48% occ), 64 regs.
// Grid (64,4) = 256 blocks -> single wave at 2 CTAs/SM.
// ---------------------------------------------------------------------------
__global__ void __launch_bounds__(NTHR, 2) lut_kernel(float* __restrict__ out) {
    extern __shared__ uint32_t smem[];
    uint32_t* sb0  = smem;                          // bits buffer 0 (16 KB)
    uint32_t* sb1  = smem + IN_BITS;                // bits buffer 1 (16 KB)
    float*    stab = (float*)(smem + 2 * IN_BITS);  // LTILE * 64 floats (64 KB)

    const int t       = threadIdx.x;
    const int l       = t & (LTILE - 1);
    const int h       = t >> 8;                     // batch half
    const int lutbase = blockIdx.x * LTILE;
    const int g0      = blockIdx.y * BC;
    const int lut     = lutbase + l;

    // Prefetch g0's bit column into buffer 0 (async).
    {
        const uint4* src = (const uint4*)g_bits[g0];
#pragma unroll
        for (int i = t; i < IN_BITS / 4; i += NTHR)
            cp_async16((uint4*)sb0 + i, src + i);
        cp_async_commit();
    }

    // Table tile load (float4, fully coalesced) overlaps the async bits copy.
    {
        const float4* gt = (const float4*)(g_sig + (size_t)lutbase * 64);
        float4* st = (float4*)stab;
#pragma unroll
        for (int i = t; i < LTILE * 16; i += NTHR) st[i] = gt[i];
    }

    const uint16_t* cp = &g_conn[(size_t)lut * KBITS];
    const int c0 = cp[0], c1 = cp[1], c2 = cp[2], c3 = cp[3], c4 = cp[4], c5 = cp[5];
    const float* trow = stab + l * 64;
    const int jbase = h * 8;

    cp_async_wait0();
    __syncthreads();

#pragma unroll 1
    for (int g = g0; g < g0 + BC; ++g) {
        uint32_t* cur = ((g - g0) & 1) ? sb1 : sb0;
        uint32_t* nxt = ((g - g0) & 1) ? sb0 : sb1;

        // Kick off next group's copy before computing this one.
        if (g + 1 < g0 + BC) {
            const uint4* src = (const uint4*)g_bits[g + 1];
#pragma unroll
            for (int i = t; i < IN_BITS / 4; i += NTHR)
                cp_async16((uint4*)nxt + i, src + i);
            cp_async_commit();
        }

        const uint32_t w0 = cur[c0], w1 = cur[c1], w2 = cur[c2];
        const uint32_t w3 = cur[c3], w4 = cur[c4], w5 = cur[c5];

        float* op = out + (size_t)(g * 32 + jbase) * NUM_LUTS + lut;
#pragma unroll
        for (int jj = 0; jj < 8; ++jj) {
            const int j = jbase + jj;
            // bits j and j+16 of each word -> two 6-bit indices at once
            uint32_t acc =   ((w0 >> j) & 0x00010001u);
            acc = acc * 2u + ((w1 >> j) & 0x00010001u);
            acc = acc * 2u + ((w2 >> j) & 0x00010001u);
            acc = acc * 2u + ((w3 >> j) & 0x00010001u);
            acc = acc * 2u + ((w4 >> j) & 0x00010001u);
            acc = acc * 2u + ((w5 >> j) & 0x00010001u);
            float vlo = trow[acc & 63u];
            float vhi = trow[acc >> 16];
            __stcs(op + (size_t)jj * NUM_LUTS, vlo);
            __stcs(op + (size_t)(jj + 16) * NUM_LUTS, vhi);
        }

        cp_async_wait0();
        __syncthreads();
    }
}

// ---------------------------------------------------------------------------
extern "C" void kernel_launch(void* const* d_in, const int* in_sizes, int n_in,
                              void* d_out, int out_size) {
    const float* x    = (const float*)d_in[0];   // (1024, 4096) f32
    const float* tab  = (const float*)d_in[1];   // (16384, 64) f32
    const int*   conn = (const int*)d_in[2];     // (16384, 6) i32 (sniffed)
    float*       out  = (float*)d_out;           // (1024, 16384) f32

    static const int SMEM = (2 * IN_BITS + LTILE * 64) * 4;  // 98304 B
    cudaFuncSetAttribute(lut_kernel, cudaFuncAttributeMaxDynamicSharedMemorySize, SMEM);

    prep_kernel<<<PACK_BLOCKS + SIG_BLOCKS + CONN_BLOCKS, 256>>>(x, tab, conn);

    dim3 gridC(NUM_LUTS / LTILE, NGROUPS / BC);          // (64, 4)
    lut_kernel<<<gridC, NTHR, SMEM>>>(out);
}

// round 7
// speedup vs baseline: 1.1912x; 1.1912x over previous
#include <cuda_runtime.h>
#include <cstdint>

#define BATCH    1024
#define IN_BITS  4096
#define NUM_LUTS 16384
#define KBITS    6
#define NGROUPS  (BATCH / 32)          // 32 groups of 32 batches
#define LTILE    256                   // luts per block (stride of transposed tile)
#define NTHR     512                   // 256 LUTs x 2 batch-halves
#define BC       8                     // batch-groups per block

#define PACK_BLOCKS (IN_BITS / 256 * NGROUPS)         // 512
#define SIGT_BLOCKS (NUM_LUTS * 64 / 16 / 256)        // 256 (16 elems/thread)
#define CONN_BLOCKS ((NUM_LUTS * KBITS + 255) / 256)  // 384

__device__ uint32_t g_bits[NGROUPS][IN_BITS];        // 512 KB
__device__ uint16_t g_conn[NUM_LUTS * KBITS];        // 196 KB
__device__ float    g_sigT[64 * NUM_LUTS];           // 4 MB, TRANSPOSED [idx][lut]

// ---------------------------------------------------------------------------
// Fused prep: [pack | sigmoid+transpose | conn] dispatched on blockIdx.x.
// ---------------------------------------------------------------------------
__global__ void __launch_bounds__(256) prep_kernel(const float* __restrict__ x,
                                                   const float* __restrict__ table,
                                                   const int* __restrict__ conn32) {
    const int b = blockIdx.x;
    if (b < PACK_BLOCKS) {
        const int g = b >> 4;
        const int p = (b & 15) * 256 + threadIdx.x;
        const float* xp = x + (size_t)(g * 32) * IN_BITS + p;
        uint32_t a = 0;
#pragma unroll
        for (int j = 0; j < 32; ++j)
            a |= (__ldg(xp + (size_t)j * IN_BITS) > 0.5f ? 1u : 0u) << j;
        g_bits[g][p] = a;
    } else if (b < PACK_BLOCKS + SIGT_BLOCKS) {
        // sigmoid + transpose: thread owns a 4-lut x 4-idx patch.
        // Reads: 4 strided float4 (L2-amplified but small); writes: 4 coalesced
        // float4 to g_sigT[idx][lut] (consecutive threads -> consecutive luts).
        const int u    = (b - PACK_BLOCKS) * 256 + threadIdx.x;
        const int lut0 = (u & 4095) * 4;
        const int idx0 = (u >> 12) * 4;
        float4 r[4];
#pragma unroll
        for (int rr = 0; rr < 4; ++rr) {
            float4 v = *(const float4*)(table + (size_t)(lut0 + rr) * 64 + idx0);
            r[rr].x = __fdividef(1.0f, 1.0f + __expf(-v.x));
            r[rr].y = __fdividef(1.0f, 1.0f + __expf(-v.y));
            r[rr].z = __fdividef(1.0f, 1.0f + __expf(-v.z));
            r[rr].w = __fdividef(1.0f, 1.0f + __expf(-v.w));
        }
#pragma unroll
        for (int k = 0; k < 4; ++k) {
            float4 o;
            const float* s = &r[0].x;   // r[rr] component k
            o.x = (&r[0].x)[k]; o.y = (&r[1].x)[k]; o.z = (&r[2].x)[k]; o.w = (&r[3].x)[k];
            (void)s;
            *(float4*)(g_sigT + (size_t)(idx0 + k) * NUM_LUTS + lut0) = o;
        }
    } else {
        // conn dtype sniff: JAX w/o x64 emits int32 despite int64 annotation;
        // true int64 LE would have all odd words == 0 (values < 4096).
        uint32_t acc = 0;
#pragma unroll
        for (int s = 1; s < 64; s += 2) acc |= (uint32_t)conn32[s];
        const bool is_i64 = (acc == 0u);
        const int i = (b - PACK_BLOCKS - SIGT_BLOCKS) * 256 + threadIdx.x;
        if (i < NUM_LUTS * KBITS) {
            int v = is_i64 ? conn32[2 * i] : conn32[i];
            g_conn[i] = (uint16_t)v;
        }
    }
}

// ---------------------------------------------------------------------------
// cp.async helpers
// ---------------------------------------------------------------------------
__device__ __forceinline__ void cp_async16(void* smem_dst, const void* gsrc) {
    uint32_t s = (uint32_t)__cvta_generic_to_shared(smem_dst);
    asm volatile("cp.async.cg.shared.global [%0], [%1], 16;\n" :: "r"(s), "l"(gsrc));
}
__device__ __forceinline__ void cp_async_commit() {
    asm volatile("cp.async.commit_group;\n" ::: "memory");
}
__device__ __forceinline__ void cp_async_wait0() {
    asm volatile("cp.async.wait_group 0;\n" ::: "memory");
}

// ---------------------------------------------------------------------------
// Main LUT kernel. block = 512 = 256 LUTs x 2 batch-halves.
// smem: 2x16 KB bit buffers (cp.async double-buffered) + 64 KB TRANSPOSED
// table tile stab[idx][l] (stride 256 -> LDS bank = lane -> conflict-free).
// idx build packs FOUR 6-bit indices per acc word (bits j, j+8, j+16, j+24).
// ---------------------------------------------------------------------------
__global__ void __launch_bounds__(NTHR, 2) lut_kernel(float* __restrict__ out) {
    extern __shared__ uint32_t smem[];
    uint32_t* sb0  = smem;                          // bits buffer 0
    uint32_t* sb1  = smem + IN_BITS;                // bits buffer 1
    float*    stab = (float*)(smem + 2 * IN_BITS);  // [64][LTILE]

    const int t       = threadIdx.x;
    const int l       = t & (LTILE - 1);
    const int h       = t >> 8;                     // batch half
    const int lutbase = blockIdx.x * LTILE;
    const int g0      = blockIdx.y * BC;
    const int lut     = lutbase + l;

    // Prefetch g0's bit column (async).
    {
        const uint4* src = (const uint4*)g_bits[g0];
#pragma unroll
        for (int i = t; i < IN_BITS / 4; i += NTHR)
            cp_async16((uint4*)sb0 + i, src + i);
        cp_async_commit();
    }

    // Transposed table tile: stab[idx][l] <- g_sigT[idx][lutbase+l].
    // Coalesced float4 reads; STS bank = lane -> conflict-free.
    {
#pragma unroll
        for (int i = t; i < 64 * (LTILE / 4); i += NTHR) {
            const int idx = i >> 6, c = (i & 63) * 4;
            *(float4*)(stab + idx * LTILE + c) =
                *(const float4*)(g_sigT + (size_t)idx * NUM_LUTS + lutbase + c);
        }
    }

    const uint16_t* cp = &g_conn[(size_t)lut * KBITS];
    const int c0 = cp[0], c1 = cp[1], c2 = cp[2], c3 = cp[3], c4 = cp[4], c5 = cp[5];
    const float* scol = stab + l;                   // this LUT's column
    const int jbase = h * 4;

    cp_async_wait0();
    __syncthreads();

#pragma unroll 1
    for (int g = g0; g < g0 + BC; ++g) {
        uint32_t* cur = ((g - g0) & 1) ? sb1 : sb0;
        uint32_t* nxt = ((g - g0) & 1) ? sb0 : sb1;

        if (g + 1 < g0 + BC) {
            const uint4* src = (const uint4*)g_bits[g + 1];
#pragma unroll
            for (int i = t; i < IN_BITS / 4; i += NTHR)
                cp_async16((uint4*)nxt + i, src + i);
            cp_async_commit();
        }

        const uint32_t w0 = cur[c0], w1 = cur[c1], w2 = cur[c2];
        const uint32_t w3 = cur[c3], w4 = cur[c4], w5 = cur[c5];

        float* op = out + (size_t)(g * 32 + jbase) * NUM_LUTS + lut;
#pragma unroll
        for (int jj = 0; jj < 4; ++jj) {
            const int j = jbase + jj;
            // four 6-bit indices at once (bits j, j+8, j+16, j+24 of each word)
            uint32_t acc =   ((w0 >> j) & 0x01010101u);
            acc = acc * 2u + ((w1 >> j) & 0x01010101u);
            acc = acc * 2u + ((w2 >> j) & 0x01010101u);
            acc = acc * 2u + ((w3 >> j) & 0x01010101u);
            acc = acc * 2u + ((w4 >> j) & 0x01010101u);
            acc = acc * 2u + ((w5 >> j) & 0x01010101u);
            const unsigned i0 = acc & 0xFFu;
            const unsigned i1 = __byte_perm(acc, 0, 0x4441);
            const unsigned i2 = __byte_perm(acc, 0, 0x4442);
            const unsigned i3 = acc >> 24;
            float v0 = scol[i0 * LTILE];            // conflict-free LDS
            float v1 = scol[i1 * LTILE];
            float v2 = scol[i2 * LTILE];
            float v3 = scol[i3 * LTILE];
            __stcs(op + (size_t)jj * NUM_LUTS, v0);
            __stcs(op + (size_t)(jj + 8)  * NUM_LUTS, v1);
            __stcs(op + (size_t)(jj + 16) * NUM_LUTS, v2);
            __stcs(op + (size_t)(jj + 24) * NUM_LUTS, v3);
        }

        cp_async_wait0();
        __syncthreads();
    }
}

// ---------------------------------------------------------------------------
extern "C" void kernel_launch(void* const* d_in, const int* in_sizes, int n_in,
                              void* d_out, int out_size) {
    const float* x    = (const float*)d_in[0];   // (1024, 4096) f32
    const float* tab  = (const float*)d_in[1];   // (16384, 64) f32
    const int*   conn = (const int*)d_in[2];     // (16384, 6) i32 (sniffed)
    float*       out  = (float*)d_out;           // (1024, 16384) f32

    static const int SMEM = (2 * IN_BITS + 64 * LTILE) * 4;  // 98304 B
    cudaFuncSetAttribute(lut_kernel, cudaFuncAttributeMaxDynamicSharedMemorySize, SMEM);

    prep_kernel<<<PACK_BLOCKS + SIGT_BLOCKS + CONN_BLOCKS, 256>>>(x, tab, conn);

    dim3 gridC(NUM_LUTS / LTILE, NGROUPS / BC);          // (64, 4)
    lut_kernel<<<gridC, NTHR, SMEM>>>(out);
}